// round 5
// baseline (speedup 1.0000x reference)
#include <cuda_runtime.h>
#include <cstdint>

// GRU-GNN fused kernel for GB300 (sm_103a).
//   red[dst[e]] = h[src[e]]  (exactly one incoming edge per node)
//   gi = x @ w_ih^T + b_ih ; gh = red @ w_hh^T + b_hh
//   r=sig(i_r+h_r); z=sig(i_z+h_z); n=tanh(i_n + r*h_n); out=(1-z)n + z*red
//
// fp32, f32x2-packed FMA over K (even/odd-k partial sums per accumulator half),
// persistent CTAs, cp.async double-buffered row tiles, weights smem-resident.

#define MTILE 64          // edges (rows) per tile
#define CTILE 16          // output columns per tile (x6 gate blocks)
#define KP    132         // padded k stride in floats (conflict-free LDS.128)
#define NTHREADS 256
#define GRID 152

#define WS_FLOATS (6 * CTILE * KP)   // 12672
#define XS_FLOATS (2 * MTILE * KP)   // 16896 per double-buffered array
#define SMEM_BYTES ((WS_FLOATS + 2 * XS_FLOATS) * 4 + 6 * MTILE * 4)

__device__ __forceinline__ void fma2(unsigned long long& a,
                                     unsigned long long b,
                                     unsigned long long c) {
    // packed f32x2 FMA: a.lo += b.lo*c.lo ; a.hi += b.hi*c.hi  (SASS FFMA2)
    asm("fma.rn.f32x2 %0, %1, %2, %0;" : "+l"(a) : "l"(b), "l"(c));
}

__device__ __forceinline__ float sum2(unsigned long long v) {
    float lo = __uint_as_float((unsigned)(v & 0xffffffffull));
    float hi = __uint_as_float((unsigned)(v >> 32));
    return lo + hi;
}

__device__ __forceinline__ float sigmoid_f(float t) {
    return __fdividef(1.0f, 1.0f + __expf(-t));
}

__device__ __forceinline__ void cp16(void* s, const void* g) {
    unsigned sa = (unsigned)__cvta_generic_to_shared(s);
    asm volatile("cp.async.cg.shared.global [%0], [%1], 16;" :: "r"(sa), "l"(g));
}
#define CP_COMMIT() asm volatile("cp.async.commit_group;")
#define CP_WAIT0()  asm volatile("cp.async.wait_group 0;")

// cp.async one (x, red) row tile: 8 iters x 2 x 16B per thread = 64 rows x 512B x2
__device__ __forceinline__ void issue_tile(float* XS, float* RS,
                                           const int* IDXN, const int* IDXS,
                                           const float* __restrict__ x,
                                           const float* __restrict__ h,
                                           int buf, int slot, int t) {
#pragma unroll
    for (int j = 0; j < 8; j++) {
        int f   = t + NTHREADS * j;      // 0..2047
        int row = f >> 5;                // 0..63
        int kq  = f & 31;                // float4 index along k
        int node = IDXN[slot * MTILE + row];
        int s    = IDXS[slot * MTILE + row];
        cp16(XS + (buf * MTILE + row) * KP + 4 * kq, x + (size_t)node * 128 + 4 * kq);
        cp16(RS + (buf * MTILE + row) * KP + 4 * kq, h + (size_t)s    * 128 + 4 * kq);
    }
}

__global__ void __launch_bounds__(NTHREADS, 1)
gru_gnn_f32x2_kernel(const float* __restrict__ x, const float* __restrict__ h,
                     const float* __restrict__ w_ih, const float* __restrict__ w_hh,
                     const float* __restrict__ b_ih, const float* __restrict__ b_hh,
                     const int* __restrict__ src, const int* __restrict__ dst,
                     float* __restrict__ out, int N, int num_mt, int total)
{
    extern __shared__ __align__(16) char smem_raw[];
    float* WS = (float*)smem_raw;            // weights [6][CTILE][KP], k-major
    float* XS = WS + WS_FLOATS;              // x tiles  [2][MTILE][KP]
    float* RS = XS + XS_FLOATS;              // red tiles[2][MTILE][KP]
    int* IDXN = (int*)(RS + XS_FLOATS);      // [3][MTILE] output node per row
    int* IDXS = IDXN + 3 * MTILE;            // [3][MTILE] gather src per row

    const int t  = threadIdx.x;
    const int tx = t & 7;    // columns: tx, tx+8 within the 16-col tile
    const int ty = t >> 3;   // rows: 2*ty, 2*ty+1
    const int G  = gridDim.x;

    int it0 = blockIdx.x;
    if (it0 >= total) return;

    // ---------------- prologue ----------------
    {
        int mt = it0 % num_mt;
        if (t < MTILE) {
            int e = mt * MTILE + t; if (e >= N) e = N - 1;
            IDXN[t] = dst[e];
            IDXS[t] = src[e];
        }
    }
    __syncthreads();
    issue_tile(XS, RS, IDXN, IDXS, x, h, /*buf=*/0, /*slot=*/0, t);
    CP_COMMIT();
    if (it0 + G < total) {
        int mt = (it0 + G) % num_mt;
        if (t < MTILE) {
            int e = mt * MTILE + t; if (e >= N) e = N - 1;
            IDXN[MTILE + t] = dst[e];
            IDXS[MTILE + t] = src[e];
        }
    }

    int cur_ct = -1;
    float bi[3][2], bh[3][2];

    // ---------------- main loop over work items (ct-major) ----------------
    for (int n = 0;; n++) {
        int it = it0 + n * G;
        if (it >= total) break;
        int buf  = n & 1;
        int slot = n % 3;
        int ct = it / num_mt;            // column tile (changes rarely)

        CP_WAIT0();                      // this tile's x/red copies retired
        __syncthreads();                 // ...visible to all; prior iter done

        bool wload = (ct != cur_ct);
        if (wload) {
            int c0 = ct * CTILE;
#pragma unroll
            for (int i = 0; i < 12; i++) {
                int f = t + NTHREADS * i;        // 3072 float4s = 6*16*32
                int rowf = f >> 5, kq = f & 31;
                int g = rowf >> 4, c = rowf & 15;
                const float* base = (g < 3) ? w_ih : w_hh;
                int g3 = (g < 3) ? g : g - 3;
                float4 v = *(const float4*)(base + ((size_t)(g3 * 128 + c0 + c)) * 128 + 4 * kq);
                *(float4*)(WS + (g * CTILE + c) * KP + 4 * kq) = v;
            }
#pragma unroll
            for (int ci = 0; ci < 2; ci++) {
                int cg = c0 + tx + ci * 8;
                bi[0][ci] = b_ih[cg];       bh[0][ci] = b_hh[cg];
                bi[1][ci] = b_ih[cg + 128]; bh[1][ci] = b_hh[cg + 128];
                bi[2][ci] = b_ih[cg + 256]; bh[2][ci] = b_hh[cg + 256];
            }
            cur_ct = ct;
        }

        // output nodes for epilogue (read before slot ring advances)
        int node0 = IDXN[slot * MTILE + 2 * ty];
        int node1 = IDXN[slot * MTILE + 2 * ty + 1];

        // prefetch next tile into the other buffer (overlaps compute)
        if (it + G < total) {
            issue_tile(XS, RS, IDXN, IDXS, x, h, buf ^ 1, (n + 1) % 3, t);
            CP_COMMIT();
        }
        // indices two tiles ahead (slot (n+2)%3: not read until next iter)
        if (it + 2 * G < total) {
            int mt2 = (it + 2 * G) % num_mt;
            int sl2 = (n + 2) % 3;
            if (t < MTILE) {
                int e = mt2 * MTILE + t; if (e >= N) e = N - 1;
                IDXN[sl2 * MTILE + t] = dst[e];
                IDXS[sl2 * MTILE + t] = src[e];
            }
        }
        if (wload) __syncthreads();      // weights visible before compute

        // ---------------- compute: 2 rows x 2 cols x 6 gates ----------------
        unsigned long long acc[2][2][6];
#pragma unroll
        for (int a = 0; a < 2; a++)
#pragma unroll
            for (int b = 0; b < 2; b++)
#pragma unroll
                for (int g = 0; g < 6; g++) acc[a][b][g] = 0ull;

        const float* xr0 = XS + (buf * MTILE + 2 * ty) * KP;
        const float* xr1 = xr0 + KP;
        const float* rr0 = RS + (buf * MTILE + 2 * ty) * KP;
        const float* rr1 = rr0 + KP;

#pragma unroll 4
        for (int k = 0; k < 128; k += 4) {
            ulonglong2 xv0 = *(const ulonglong2*)(xr0 + k);
            ulonglong2 xv1 = *(const ulonglong2*)(xr1 + k);
            ulonglong2 rv0 = *(const ulonglong2*)(rr0 + k);
            ulonglong2 rv1 = *(const ulonglong2*)(rr1 + k);
#pragma unroll
            for (int g = 0; g < 6; g++) {
                ulonglong2 a0 = (g < 3) ? xv0 : rv0;   // compile-time select
                ulonglong2 a1 = (g < 3) ? xv1 : rv1;
#pragma unroll
                for (int ci = 0; ci < 2; ci++) {
                    ulonglong2 wv = *(const ulonglong2*)(
                        WS + (g * CTILE + tx + ci * 8) * KP + k);
                    fma2(acc[0][ci][g], wv.x, a0.x);
                    fma2(acc[0][ci][g], wv.y, a0.y);
                    fma2(acc[1][ci][g], wv.x, a1.x);
                    fma2(acc[1][ci][g], wv.y, a1.y);
                }
            }
        }

        // ---------------- GRU epilogue ----------------
        int c0 = ct * CTILE;
#pragma unroll
        for (int ri = 0; ri < 2; ri++) {
            int row  = 2 * ty + ri;
            int node = ri ? node1 : node0;
#pragma unroll
            for (int ci = 0; ci < 2; ci++) {
                int cg = c0 + tx + ci * 8;
                float gr = sum2(acc[ri][ci][0]) + bi[0][ci];
                float gz = sum2(acc[ri][ci][1]) + bi[1][ci];
                float gn = sum2(acc[ri][ci][2]) + bi[2][ci];
                float hr = sum2(acc[ri][ci][3]) + bh[0][ci];
                float hz = sum2(acc[ri][ci][4]) + bh[1][ci];
                float hn = sum2(acc[ri][ci][5]) + bh[2][ci];
                float rg = sigmoid_f(gr + hr);
                float zg = sigmoid_f(gz + hz);
                float ng = tanhf(gn + rg * hn);
                float red = RS[(buf * MTILE + row) * KP + cg];
                out[(size_t)node * 128 + cg] = (1.0f - zg) * ng + zg * red;
            }
        }
    }
}

extern "C" void kernel_launch(void* const* d_in, const int* in_sizes, int n_in,
                              void* d_out, int out_size) {
    const float* x    = (const float*)d_in[0];
    const float* h    = (const float*)d_in[1];
    const float* w_ih = (const float*)d_in[2];
    const float* w_hh = (const float*)d_in[3];
    const float* b_ih = (const float*)d_in[4];
    const float* b_hh = (const float*)d_in[5];
    const int*   src  = (const int*)d_in[6];
    const int*   dst  = (const int*)d_in[7];
    float* out = (float*)d_out;

    int N = in_sizes[6];                 // #edges == #nodes
    int num_mt = (N + MTILE - 1) / MTILE;
    int total  = (128 / CTILE) * num_mt; // 8 column tiles

    cudaFuncSetAttribute(gru_gnn_f32x2_kernel,
                         cudaFuncAttributeMaxDynamicSharedMemorySize, SMEM_BYTES);

    int grid = GRID < total ? GRID : total;
    gru_gnn_f32x2_kernel<<<grid, NTHREADS, SMEM_BYTES>>>(
        x, h, w_ih, w_hh, b_ih, b_hh, src, dst, out, N, num_mt, total);
}